// round 1
// baseline (speedup 1.0000x reference)
#include <cuda_runtime.h>
#include <math.h>
#include <float.h>

#define BATCH 32
#define NTOK  576
#define NK    577      // N + 1 (with CLS)
#define CH    1024
#define LTOP  72       // N/8
#define NCOMPL 504     // N - L
#define KCL   32

// ---------------- device scratch (static, allocation-free) ----------------
__device__ float g_logits[BATCH][NK];
__device__ float g_ninv[BATCH][NTOK];
__device__ float g_attn[BATCH][NTOK];
__device__ int   g_idx[BATCH][LTOP];
__device__ int   g_compl[BATCH][NCOMPL];
__device__ float g_simA[BATCH][LTOP][NTOK];   // split-K half 0 (raw dots)
__device__ float g_simB[BATCH][LTOP][NTOK];   // split-K half 1

// ---------------- K1: logits (q0 . key_r) and per-row inv-norms ----------------
__global__ __launch_bounds__(256) void k_logits(const float* __restrict__ keys,
                                                const float* __restrict__ queries) {
    int gw   = (blockIdx.x * blockDim.x + threadIdx.x) >> 5;
    int lane = threadIdx.x & 31;
    if (gw >= BATCH * NK) return;
    int b = gw / NK;
    int r = gw - b * NK;
    const float4* q = (const float4*)(queries + (size_t)b * NK * CH);      // row 0 only
    const float4* k = (const float4*)(keys + ((size_t)b * NK + r) * CH);
    float dot = 0.f, ss = 0.f;
#pragma unroll
    for (int i = 0; i < 8; i++) {
        float4 kv = k[i * 32 + lane];
        float4 qv = q[i * 32 + lane];
        dot += kv.x * qv.x + kv.y * qv.y + kv.z * qv.z + kv.w * qv.w;
        ss  += kv.x * kv.x + kv.y * kv.y + kv.z * kv.z + kv.w * kv.w;
    }
#pragma unroll
    for (int o = 16; o > 0; o >>= 1) {
        dot += __shfl_xor_sync(0xffffffffu, dot, o);
        ss  += __shfl_xor_sync(0xffffffffu, ss, o);
    }
    if (lane == 0) {
        g_logits[b][r] = dot * 0.03125f;   // C^-0.5
        if (r >= 1) g_ninv[b][r - 1] = rsqrtf(ss + 1e-12f);
    }
}

// ---------------- K2: softmax over 577, top-L rank select, complement ----------------
__global__ __launch_bounds__(640) void k_softmax_topk() {
    __shared__ float sl[NK];
    __shared__ float sa[NTOK];
    __shared__ int   sflag[NTOK];
    __shared__ float red[640];
    int b = blockIdx.x;
    int t = threadIdx.x;

    if (t < NK) sl[t] = g_logits[b][t];
    __syncthreads();

    // max reduce
    red[t] = (t < NK) ? sl[t] : -FLT_MAX;
    __syncthreads();
    if (t < 128) red[t] = fmaxf(red[t], red[t + 512]);
    __syncthreads();
    for (int s = 256; s > 0; s >>= 1) {
        if (t < s) red[t] = fmaxf(red[t], red[t + s]);
        __syncthreads();
    }
    float mx = red[0];
    __syncthreads();

    // exp + sum reduce
    float e = 0.f;
    if (t < NK) { e = expf(sl[t] - mx); sl[t] = e; }
    red[t] = e;
    __syncthreads();
    if (t < 128) red[t] += red[t + 512];
    __syncthreads();
    for (int s = 256; s > 0; s >>= 1) {
        if (t < s) red[t] += red[t + s];
        __syncthreads();
    }
    float inv_sum = 1.0f / red[0];
    __syncthreads();

    if (t >= 1 && t < NK) {
        float a = sl[t] * inv_sum;
        sa[t - 1] = a;
        g_attn[b][t - 1] = a;
    }
    __syncthreads();

    // rank = #(strictly greater) + #(equal with lower index)  -> strict total order,
    // reproduces jax.lax.top_k stable descending order exactly.
    if (t < NTOK) {
        float my = sa[t];
        int cnt = 0;
        for (int m = 0; m < NTOK; m++) {
            float v = sa[m];
            cnt += (v > my) || (v == my && m < t);
        }
        sflag[t] = (cnt < LTOP);
        if (cnt < LTOP) g_idx[b][cnt] = t;
    }
    __syncthreads();

    // complement, ascending (matches sort of masked arange)
    if (t < NTOK && !sflag[t]) {
        int nb = 0;
        for (int m = 0; m < t; m++) nb += sflag[m];
        g_compl[b][t - nb] = t;
    }
}

// ---------------- K3: sim raw-dot GEMM  A(72xK-gathered) x B(576xK)^T, split-K=2 ----------------
#define BM 72
#define BN 64
#define BK 16
__global__ __launch_bounds__(288) void k_sim(const float* __restrict__ keys) {
    __shared__ float sA[BK][BM];
    __shared__ float sB[BK][BN];
    __shared__ int   sidx[BM];

    int b  = blockIdx.y;
    int n0 = blockIdx.x * BN;
    int kz = blockIdx.z;           // split-K half
    int tid = threadIdx.x;

    if (tid < BM) sidx[tid] = g_idx[b][tid];
    __syncthreads();

    int ty = tid >> 4;             // 0..17  (M)
    int tx = tid & 15;             // 0..15  (N)

    const float* kb = keys + (size_t)b * NK * CH;

    // A loader mapping: 288 threads load 72x16 floats as float4
    int am  = tid >> 2;            // 0..71
    int akq = tid & 3;
    const float4* aptr = (const float4*)(kb + (size_t)(sidx[am] + 1) * CH) + akq;
    // B loader mapping: first 256 threads load 64x16 floats as float4
    int bn  = tid >> 2;            // 0..71, valid < 64
    int bkq = tid & 3;
    const float4* bptr = (const float4*)(kb + (size_t)(1 + n0 + (bn & 63)) * CH) + bkq;

    float acc[4][4] = {};
    int k0 = kz * 512;
    for (int it = 0; it < 32; it++, k0 += BK) {
        float4 av = aptr[k0 >> 2];
        sA[akq * 4 + 0][am] = av.x;
        sA[akq * 4 + 1][am] = av.y;
        sA[akq * 4 + 2][am] = av.z;
        sA[akq * 4 + 3][am] = av.w;
        if (tid < 256) {
            float4 bv = bptr[k0 >> 2];
            sB[bkq * 4 + 0][bn] = bv.x;
            sB[bkq * 4 + 1][bn] = bv.y;
            sB[bkq * 4 + 2][bn] = bv.z;
            sB[bkq * 4 + 3][bn] = bv.w;
        }
        __syncthreads();
#pragma unroll
        for (int k = 0; k < BK; k++) {
            float4 a  = *(const float4*)&sA[k][ty * 4];
            float4 bb = *(const float4*)&sB[k][tx * 4];
            acc[0][0] += a.x * bb.x; acc[0][1] += a.x * bb.y; acc[0][2] += a.x * bb.z; acc[0][3] += a.x * bb.w;
            acc[1][0] += a.y * bb.x; acc[1][1] += a.y * bb.y; acc[1][2] += a.y * bb.z; acc[1][3] += a.y * bb.w;
            acc[2][0] += a.z * bb.x; acc[2][1] += a.z * bb.y; acc[2][2] += a.z * bb.z; acc[2][3] += a.z * bb.w;
            acc[3][0] += a.w * bb.x; acc[3][1] += a.w * bb.y; acc[3][2] += a.w * bb.z; acc[3][3] += a.w * bb.w;
        }
        __syncthreads();
    }

    float* dst = kz ? &g_simB[0][0][0] : &g_simA[0][0][0];
#pragma unroll
    for (int i = 0; i < 4; i++) {
        float4 o = make_float4(acc[i][0], acc[i][1], acc[i][2], acc[i][3]);
        *(float4*)&dst[((size_t)b * LTOP + (ty * 4 + i)) * NTOK + n0 + tx * 4] = o;
    }
}

// ---------------- K4: per (b,l) top-32 select + weighted merge ----------------
__global__ __launch_bounds__(256) void k_merge(const float* __restrict__ x,
                                               float* __restrict__ out) {
    __shared__ float s[NTOK];
    __shared__ int   sel[KCL];
    __shared__ float w[KCL];
    int b = blockIdx.y;
    int l = blockIdx.x;
    int t = threadIdx.x;

    int idxl = g_idx[b][l];
    for (int m = t; m < NTOK; m += 256)
        s[m] = (g_simA[b][l][m] + g_simB[b][l][m]) * g_ninv[b][m];
    __syncthreads();
    if (t == 0) s[idxl] = -FLT_MAX;   // diagonal (self) mask
    __syncthreads();

    // rank-based top-32; sel[rank] = m  -> deterministic, descending order (matches cidx order)
    for (int m = t; m < NTOK; m += 256) {
        float my = s[m];
        int c = 0;
        for (int m2 = 0; m2 < NTOK; m2++) {
            float v = s[m2];
            c += (v > my) || (v == my && m2 < m);
        }
        if (c < KCL) sel[c] = m;
    }
    __syncthreads();
    if (t < KCL) w[t] = g_attn[b][sel[t]];
    __syncthreads();

    const float4* xb = (const float4*)(x + (size_t)b * NTOK * CH);
    float4 acc = xb[(size_t)idxl * 256 + t];
#pragma unroll 8
    for (int j = 0; j < KCL; j++) {
        float4 v = xb[(size_t)sel[j] * 256 + t];
        float wj = w[j];
        acc.x += wj * v.x; acc.y += wj * v.y; acc.z += wj * v.z; acc.w += wj * v.w;
    }
    ((float4*)(out + ((size_t)b * (LTOP + 1) + l) * CH))[t] = acc;
}

// ---------------- K5: extra = sum over complement of attn * x ----------------
__global__ __launch_bounds__(256) void k_extra(const float* __restrict__ x,
                                               float* __restrict__ out) {
    __shared__ float wa[NCOMPL];
    __shared__ int   tk[NCOMPL];
    int b = blockIdx.x;
    int t = threadIdx.x;
    for (int j = t; j < NCOMPL; j += 256) {
        int tok = g_compl[b][j];
        tk[j] = tok;
        wa[j] = g_attn[b][tok];
    }
    __syncthreads();
    const float4* xb = (const float4*)(x + (size_t)b * NTOK * CH);
    float4 acc = make_float4(0.f, 0.f, 0.f, 0.f);
    for (int j = 0; j < NCOMPL; j++) {
        float4 v = xb[(size_t)tk[j] * 256 + t];
        float wj = wa[j];
        acc.x += wj * v.x; acc.y += wj * v.y; acc.z += wj * v.z; acc.w += wj * v.w;
    }
    ((float4*)(out + ((size_t)b * (LTOP + 1) + LTOP) * CH))[t] = acc;
}

// ---------------- launch ----------------
extern "C" void kernel_launch(void* const* d_in, const int* in_sizes, int n_in,
                              void* d_out, int out_size) {
    const float* x       = (const float*)d_in[0];   // image_features [32,576,1024]
    const float* keys    = (const float*)d_in[1];   // keys           [32,577,1024]
    const float* queries = (const float*)d_in[2];   // queries        [32,577,1024]
    float* out = (float*)d_out;                     // [32,73,1024]

    int nwarps = BATCH * NK;                        // 18464 row-dots
    k_logits<<<(nwarps * 32 + 255) / 256, 256>>>(keys, queries);
    k_softmax_topk<<<BATCH, 640>>>();
    dim3 g3(NTOK / BN, BATCH, 2);                   // 9 x 32 x 2 = 576 blocks
    k_sim<<<g3, 288>>>(keys);
    dim3 g4(LTOP, BATCH);                           // 72 x 32 = 2304 blocks
    k_merge<<<g4, 256>>>(x, out);
    k_extra<<<BATCH, 256>>>(x, out);
}

// round 2
// speedup vs baseline: 2.1359x; 2.1359x over previous
#include <cuda_runtime.h>
#include <math.h>
#include <float.h>

#define BATCH 32
#define NTOK  576
#define NK    577      // N + 1 (with CLS)
#define CH    1024
#define LTOP  72       // N/8
#define NCOMPL 504     // N - L
#define KCL   32
#define NSEG  8
#define SEGTOK (NCOMPL / NSEG)   // 63

// ---------------- device scratch (static, allocation-free) ----------------
__device__ float g_logits[BATCH][NK];
__device__ float g_ninv[BATCH][NTOK];
__device__ float g_attn[BATCH][NTOK];
__device__ int   g_idx[BATCH][LTOP];
__device__ int   g_compl[BATCH][NCOMPL];
__device__ float g_simA[BATCH][LTOP][NTOK];   // split-K half 0 (raw dots)
__device__ float g_simB[BATCH][LTOP][NTOK];   // split-K half 1
__device__ int   g_sel[BATCH][LTOP][KCL];
__device__ float g_xpart[BATCH][NSEG][CH];

// ---------------- K1: logits (q0 . key_r) and per-row inv-norms ----------------
__global__ __launch_bounds__(256) void k_logits(const float* __restrict__ keys,
                                                const float* __restrict__ queries) {
    int gw   = (blockIdx.x * blockDim.x + threadIdx.x) >> 5;
    int lane = threadIdx.x & 31;
    if (gw >= BATCH * NK) return;
    int b = gw / NK;
    int r = gw - b * NK;
    const float4* q = (const float4*)(queries + (size_t)b * NK * CH);      // row 0 only
    const float4* k = (const float4*)(keys + ((size_t)b * NK + r) * CH);
    float dot = 0.f, ss = 0.f;
#pragma unroll
    for (int i = 0; i < 8; i++) {
        float4 kv = k[i * 32 + lane];
        float4 qv = q[i * 32 + lane];
        dot += kv.x * qv.x + kv.y * qv.y + kv.z * qv.z + kv.w * qv.w;
        ss  += kv.x * kv.x + kv.y * kv.y + kv.z * kv.z + kv.w * kv.w;
    }
#pragma unroll
    for (int o = 16; o > 0; o >>= 1) {
        dot += __shfl_xor_sync(0xffffffffu, dot, o);
        ss  += __shfl_xor_sync(0xffffffffu, ss, o);
    }
    if (lane == 0) {
        g_logits[b][r] = dot * 0.03125f;   // C^-0.5
        if (r >= 1) g_ninv[b][r - 1] = rsqrtf(ss + 1e-12f);
    }
}

// ---------------- K2: softmax over 577, top-L rank select, complement ----------------
__global__ __launch_bounds__(640) void k_softmax_topk() {
    __shared__ float sl[NK];
    __shared__ float sa[NTOK];
    __shared__ int   sflag[NTOK];
    __shared__ float red[640];
    int b = blockIdx.x;
    int t = threadIdx.x;

    if (t < NK) sl[t] = g_logits[b][t];
    __syncthreads();

    // max reduce
    red[t] = (t < NK) ? sl[t] : -FLT_MAX;
    __syncthreads();
    if (t < 128) red[t] = fmaxf(red[t], red[t + 512]);
    __syncthreads();
    for (int s = 256; s > 0; s >>= 1) {
        if (t < s) red[t] = fmaxf(red[t], red[t + s]);
        __syncthreads();
    }
    float mx = red[0];
    __syncthreads();

    // exp + sum reduce
    float e = 0.f;
    if (t < NK) { e = expf(sl[t] - mx); sl[t] = e; }
    red[t] = e;
    __syncthreads();
    if (t < 128) red[t] += red[t + 512];
    __syncthreads();
    for (int s = 256; s > 0; s >>= 1) {
        if (t < s) red[t] += red[t + s];
        __syncthreads();
    }
    float inv_sum = 1.0f / red[0];
    __syncthreads();

    if (t >= 1 && t < NK) {
        float a = sl[t] * inv_sum;
        sa[t - 1] = a;
        g_attn[b][t - 1] = a;
    }
    __syncthreads();

    // rank = #(strictly greater) + #(equal with lower index)  -> strict total order,
    // reproduces jax.lax.top_k stable descending order exactly.
    if (t < NTOK) {
        float my = sa[t];
        int cnt = 0;
        for (int m = 0; m < NTOK; m++) {
            float v = sa[m];
            cnt += (v > my) || (v == my && m < t);
        }
        sflag[t] = (cnt < LTOP);
        if (cnt < LTOP) g_idx[b][cnt] = t;
    }
    __syncthreads();

    // complement, ascending (matches sort of masked arange)
    if (t < NTOK && !sflag[t]) {
        int nb = 0;
        for (int m = 0; m < t; m++) nb += sflag[m];
        g_compl[b][t - nb] = t;
    }
}

// ---------------- K3: sim raw-dot GEMM  A(72xK-gathered) x B(576xK)^T, split-K=2 ----------------
#define BM 72
#define BN 64
#define BK 16
__global__ __launch_bounds__(288) void k_sim(const float* __restrict__ keys) {
    __shared__ float sA[BK][BM];
    __shared__ float sB[BK][BN];
    __shared__ int   sidx[BM];

    int b  = blockIdx.y;
    int n0 = blockIdx.x * BN;
    int kz = blockIdx.z;           // split-K half
    int tid = threadIdx.x;

    if (tid < BM) sidx[tid] = g_idx[b][tid];
    __syncthreads();

    int ty = tid >> 4;             // 0..17  (M)
    int tx = tid & 15;             // 0..15  (N)

    const float* kb = keys + (size_t)b * NK * CH;

    // A loader mapping: 288 threads load 72x16 floats as float4
    int am  = tid >> 2;            // 0..71
    int akq = tid & 3;
    const float4* aptr = (const float4*)(kb + (size_t)(sidx[am] + 1) * CH) + akq;
    // B loader mapping: first 256 threads load 64x16 floats as float4
    int bn  = tid >> 2;            // 0..71, valid < 64
    int bkq = tid & 3;
    const float4* bptr = (const float4*)(kb + (size_t)(1 + n0 + (bn & 63)) * CH) + bkq;

    float acc[4][4] = {};
    int k0 = kz * 512;
    for (int it = 0; it < 32; it++, k0 += BK) {
        float4 av = aptr[k0 >> 2];
        sA[akq * 4 + 0][am] = av.x;
        sA[akq * 4 + 1][am] = av.y;
        sA[akq * 4 + 2][am] = av.z;
        sA[akq * 4 + 3][am] = av.w;
        if (tid < 256) {
            float4 bv = bptr[k0 >> 2];
            sB[bkq * 4 + 0][bn] = bv.x;
            sB[bkq * 4 + 1][bn] = bv.y;
            sB[bkq * 4 + 2][bn] = bv.z;
            sB[bkq * 4 + 3][bn] = bv.w;
        }
        __syncthreads();
#pragma unroll
        for (int k = 0; k < BK; k++) {
            float4 a  = *(const float4*)&sA[k][ty * 4];
            float4 bb = *(const float4*)&sB[k][tx * 4];
            acc[0][0] += a.x * bb.x; acc[0][1] += a.x * bb.y; acc[0][2] += a.x * bb.z; acc[0][3] += a.x * bb.w;
            acc[1][0] += a.y * bb.x; acc[1][1] += a.y * bb.y; acc[1][2] += a.y * bb.z; acc[1][3] += a.y * bb.w;
            acc[2][0] += a.z * bb.x; acc[2][1] += a.z * bb.y; acc[2][2] += a.z * bb.z; acc[2][3] += a.z * bb.w;
            acc[3][0] += a.w * bb.x; acc[3][1] += a.w * bb.y; acc[3][2] += a.w * bb.z; acc[3][3] += a.w * bb.w;
        }
        __syncthreads();
    }

    float* dst = kz ? &g_simB[0][0][0] : &g_simA[0][0][0];
#pragma unroll
    for (int i = 0; i < 4; i++) {
        float4 o = make_float4(acc[i][0], acc[i][1], acc[i][2], acc[i][3]);
        *(float4*)&dst[((size_t)b * LTOP + (ty * 4 + i)) * NTOK + n0 + tx * 4] = o;
    }
}

// ---------------- K4a: per (b,l) top-32 selection, one warp per problem ----------------
// Packed key = (ordered_f32 << 32) | (NTOK - m): descending value, ascending index
// on ties -> exact jax.lax.top_k order. Iterative 32x warp argmax with incremental
// per-lane local max (only the winning lane rescans its 18 slots).
__global__ __launch_bounds__(256) void k_select() {
    int gw   = blockIdx.x * 8 + (threadIdx.x >> 5);
    int lane = threadIdx.x & 31;
    if (gw >= BATCH * LTOP) return;
    int b = gw / LTOP;
    int l = gw - b * LTOP;
    int idxl = g_idx[b][l];

    const float* __restrict__ pa = &g_simA[b][l][0];
    const float* __restrict__ pb = &g_simB[b][l][0];
    const float* __restrict__ pn = &g_ninv[b][0];

    unsigned long long key[18];
#pragma unroll
    for (int j = 0; j < 18; j++) {
        int m = lane + 32 * j;
        float v = (pa[m] + pb[m]) * pn[m];
        unsigned u = __float_as_uint(v);
        u = (u & 0x80000000u) ? ~u : (u | 0x80000000u);
        key[j] = ((unsigned long long)u << 32) | (unsigned)(NTOK - m);
        if (m == idxl) key[j] = 0ULL;   // diagonal (self) mask
    }
    unsigned long long bestk = 0ULL;
    int bestj = 0;
#pragma unroll
    for (int j = 0; j < 18; j++)
        if (key[j] > bestk) { bestk = key[j]; bestj = j; }

    for (int it = 0; it < KCL; it++) {
        unsigned long long wmax = bestk;
#pragma unroll
        for (int off = 16; off > 0; off >>= 1) {
            unsigned long long o = __shfl_xor_sync(0xffffffffu, wmax, off);
            if (o > wmax) wmax = o;
        }
        if (bestk == wmax) {            // unique winner (index embedded in key)
            g_sel[b][l][it] = NTOK - (int)(unsigned)(wmax & 0xffffffffULL);
#pragma unroll
            for (int j = 0; j < 18; j++)
                if (j == bestj) key[j] = 0ULL;
            bestk = 0ULL; bestj = 0;
#pragma unroll
            for (int j = 0; j < 18; j++)
                if (key[j] > bestk) { bestk = key[j]; bestj = j; }
        }
    }
}

// ---------------- K4b: gather + weighted merge (memory-bound) ----------------
__global__ __launch_bounds__(256) void k_merge(const float* __restrict__ x,
                                               float* __restrict__ out) {
    __shared__ int   sel[KCL];
    __shared__ float w[KCL];
    int b = blockIdx.y;
    int l = blockIdx.x;
    int t = threadIdx.x;

    if (t < KCL) {
        int m = g_sel[b][l][t];
        sel[t] = m;
        w[t]   = g_attn[b][m];
    }
    __syncthreads();

    int idxl = g_idx[b][l];
    const float4* xb = (const float4*)(x + (size_t)b * NTOK * CH);
    float4 acc = xb[(size_t)idxl * 256 + t];
#pragma unroll 8
    for (int j = 0; j < KCL; j++) {
        float4 v = xb[(size_t)sel[j] * 256 + t];
        float wj = w[j];
        acc.x += wj * v.x; acc.y += wj * v.y; acc.z += wj * v.z; acc.w += wj * v.w;
    }
    ((float4*)(out + ((size_t)b * (LTOP + 1) + l) * CH))[t] = acc;
}

// ---------------- K5a: extra partial sums, 8 token-segments per batch ----------------
__global__ __launch_bounds__(256) void k_extra_part(const float* __restrict__ x) {
    __shared__ float wa[SEGTOK];
    __shared__ int   tk[SEGTOK];
    int b = blockIdx.y;
    int s = blockIdx.x;
    int t = threadIdx.x;
    if (t < SEGTOK) {
        int tok = g_compl[b][s * SEGTOK + t];
        tk[t] = tok;
        wa[t] = g_attn[b][tok];
    }
    __syncthreads();
    const float4* xb = (const float4*)(x + (size_t)b * NTOK * CH);
    float4 acc = make_float4(0.f, 0.f, 0.f, 0.f);
#pragma unroll 7
    for (int j = 0; j < SEGTOK; j++) {
        float4 v = xb[(size_t)tk[j] * 256 + t];
        float wj = wa[j];
        acc.x += wj * v.x; acc.y += wj * v.y; acc.z += wj * v.z; acc.w += wj * v.w;
    }
    ((float4*)&g_xpart[b][s][0])[t] = acc;
}

// ---------------- K5b: reduce the 8 partials into the extra row ----------------
__global__ __launch_bounds__(256) void k_extra_red(float* __restrict__ out) {
    int b = blockIdx.x;
    int t = threadIdx.x;
    float4 acc = make_float4(0.f, 0.f, 0.f, 0.f);
#pragma unroll
    for (int s = 0; s < NSEG; s++) {
        float4 v = ((const float4*)&g_xpart[b][s][0])[t];
        acc.x += v.x; acc.y += v.y; acc.z += v.z; acc.w += v.w;
    }
    ((float4*)(out + ((size_t)b * (LTOP + 1) + LTOP) * CH))[t] = acc;
}

// ---------------- launch ----------------
extern "C" void kernel_launch(void* const* d_in, const int* in_sizes, int n_in,
                              void* d_out, int out_size) {
    const float* x       = (const float*)d_in[0];   // image_features [32,576,1024]
    const float* keys    = (const float*)d_in[1];   // keys           [32,577,1024]
    const float* queries = (const float*)d_in[2];   // queries        [32,577,1024]
    float* out = (float*)d_out;                     // [32,73,1024]

    int nwarps = BATCH * NK;                        // 18464 row-dots
    k_logits<<<(nwarps * 32 + 255) / 256, 256>>>(keys, queries);
    k_softmax_topk<<<BATCH, 640>>>();
    dim3 g3(NTOK / BN, BATCH, 2);                   // 9 x 32 x 2 = 576 blocks
    k_sim<<<g3, 288>>>(keys);
    k_select<<<(BATCH * LTOP) / 8, 256>>>();        // 288 blocks, 1 warp per (b,l)
    dim3 g4(LTOP, BATCH);                           // 72 x 32 = 2304 blocks
    k_merge<<<g4, 256>>>(x, out);
    dim3 g5(NSEG, BATCH);                           // 8 x 32 = 256 blocks
    k_extra_part<<<g5, 256>>>(x);
    k_extra_red<<<BATCH, 256>>>(out);
}

// round 3
// speedup vs baseline: 2.1363x; 1.0002x over previous
#include <cuda_runtime.h>
#include <math.h>
#include <float.h>

#define BATCH 32
#define NTOK  576
#define NK    577      // N + 1 (with CLS)
#define CH    1024
#define LTOP  72       // N/8
#define NCOMPL 504     // N - L
#define KCL   32
#define NSEG  8
#define SEGTOK (NCOMPL / NSEG)   // 63

// ---------------- device scratch (static, allocation-free) ----------------
__device__ float g_logits[BATCH][NK];
__device__ float g_ninv[BATCH][NTOK];
__device__ float g_attn[BATCH][NTOK];
__device__ int   g_idx[BATCH][LTOP];
__device__ int   g_compl[BATCH][NCOMPL];
__device__ float g_simA[BATCH][LTOP][NTOK];   // split-K half 0 (raw dots)
__device__ float g_simB[BATCH][LTOP][NTOK];   // split-K half 1
__device__ int   g_sel[BATCH][LTOP][KCL];
__device__ float g_xpart[BATCH][NSEG][CH];

// ---------------- K1: logits (q0 . key_r) and per-row inv-norms ----------------
__global__ __launch_bounds__(256) void k_logits(const float* __restrict__ keys,
                                                const float* __restrict__ queries) {
    int gw   = (blockIdx.x * blockDim.x + threadIdx.x) >> 5;
    int lane = threadIdx.x & 31;
    if (gw >= BATCH * NK) return;
    int b = gw / NK;
    int r = gw - b * NK;
    const float4* q = (const float4*)(queries + (size_t)b * NK * CH);      // row 0 only
    const float4* k = (const float4*)(keys + ((size_t)b * NK + r) * CH);
    float dot = 0.f, ss = 0.f;
#pragma unroll
    for (int i = 0; i < 8; i++) {
        float4 kv = k[i * 32 + lane];
        float4 qv = q[i * 32 + lane];
        dot += kv.x * qv.x + kv.y * qv.y + kv.z * qv.z + kv.w * qv.w;
        ss  += kv.x * kv.x + kv.y * kv.y + kv.z * kv.z + kv.w * kv.w;
    }
#pragma unroll
    for (int o = 16; o > 0; o >>= 1) {
        dot += __shfl_xor_sync(0xffffffffu, dot, o);
        ss  += __shfl_xor_sync(0xffffffffu, ss, o);
    }
    if (lane == 0) {
        g_logits[b][r] = dot * 0.03125f;   // C^-0.5
        if (r >= 1) g_ninv[b][r - 1] = rsqrtf(ss + 1e-12f);
    }
}

// ---------------- K2: softmax over 577, top-L rank select, complement ----------------
__global__ __launch_bounds__(640) void k_softmax_topk() {
    __shared__ float sl[NK];
    __shared__ float sa[NTOK];
    __shared__ int   sflag[NTOK];
    __shared__ float red[640];
    int b = blockIdx.x;
    int t = threadIdx.x;

    if (t < NK) sl[t] = g_logits[b][t];
    __syncthreads();

    // max reduce
    red[t] = (t < NK) ? sl[t] : -FLT_MAX;
    __syncthreads();
    if (t < 128) red[t] = fmaxf(red[t], red[t + 512]);
    __syncthreads();
    for (int s = 256; s > 0; s >>= 1) {
        if (t < s) red[t] = fmaxf(red[t], red[t + s]);
        __syncthreads();
    }
    float mx = red[0];
    __syncthreads();

    // exp + sum reduce
    float e = 0.f;
    if (t < NK) { e = expf(sl[t] - mx); sl[t] = e; }
    red[t] = e;
    __syncthreads();
    if (t < 128) red[t] += red[t + 512];
    __syncthreads();
    for (int s = 256; s > 0; s >>= 1) {
        if (t < s) red[t] += red[t + s];
        __syncthreads();
    }
    float inv_sum = 1.0f / red[0];
    __syncthreads();

    if (t >= 1 && t < NK) {
        float a = sl[t] * inv_sum;
        sa[t - 1] = a;
        g_attn[b][t - 1] = a;
    }
    __syncthreads();

    // rank = #(strictly greater) + #(equal with lower index)  -> strict total order,
    // reproduces jax.lax.top_k stable descending order exactly.
    if (t < NTOK) {
        float my = sa[t];
        int cnt = 0;
        for (int m = 0; m < NTOK; m++) {
            float v = sa[m];
            cnt += (v > my) || (v == my && m < t);
        }
        sflag[t] = (cnt < LTOP);
        if (cnt < LTOP) g_idx[b][cnt] = t;
    }
    __syncthreads();

    // complement, ascending (matches sort of masked arange)
    if (t < NTOK && !sflag[t]) {
        int nb = 0;
        for (int m = 0; m < t; m++) nb += sflag[m];
        g_compl[b][t - nb] = t;
    }
}

// ---------------- K3: sim raw-dot GEMM  A(72xK-gathered) x B(576xK)^T, split-K=2 ----------------
#define BM 72
#define BN 64
#define BK 16
__global__ __launch_bounds__(288) void k_sim(const float* __restrict__ keys) {
    __shared__ float sA[BK][BM];
    __shared__ float sB[BK][BN];
    __shared__ int   sidx[BM];

    int b  = blockIdx.y;
    int n0 = blockIdx.x * BN;
    int kz = blockIdx.z;           // split-K half
    int tid = threadIdx.x;

    if (tid < BM) sidx[tid] = g_idx[b][tid];
    __syncthreads();

    int ty = tid >> 4;             // 0..17  (M)
    int tx = tid & 15;             // 0..15  (N)

    const float* kb = keys + (size_t)b * NK * CH;

    // A loader mapping: 288 threads load 72x16 floats as float4
    int am  = tid >> 2;            // 0..71
    int akq = tid & 3;
    const float4* aptr = (const float4*)(kb + (size_t)(sidx[am] + 1) * CH) + akq;
    // B loader mapping: first 256 threads load 64x16 floats as float4
    int bn  = tid >> 2;            // 0..71, valid < 64
    int bkq = tid & 3;
    const float4* bptr = (const float4*)(kb + (size_t)(1 + n0 + (bn & 63)) * CH) + bkq;

    float acc[4][4] = {};
    int k0 = kz * 512;
    for (int it = 0; it < 32; it++, k0 += BK) {
        float4 av = aptr[k0 >> 2];
        sA[akq * 4 + 0][am] = av.x;
        sA[akq * 4 + 1][am] = av.y;
        sA[akq * 4 + 2][am] = av.z;
        sA[akq * 4 + 3][am] = av.w;
        if (tid < 256) {
            float4 bv = bptr[k0 >> 2];
            sB[bkq * 4 + 0][bn] = bv.x;
            sB[bkq * 4 + 1][bn] = bv.y;
            sB[bkq * 4 + 2][bn] = bv.z;
            sB[bkq * 4 + 3][bn] = bv.w;
        }
        __syncthreads();
#pragma unroll
        for (int k = 0; k < BK; k++) {
            float4 a  = *(const float4*)&sA[k][ty * 4];
            float4 bb = *(const float4*)&sB[k][tx * 4];
            acc[0][0] += a.x * bb.x; acc[0][1] += a.x * bb.y; acc[0][2] += a.x * bb.z; acc[0][3] += a.x * bb.w;
            acc[1][0] += a.y * bb.x; acc[1][1] += a.y * bb.y; acc[1][2] += a.y * bb.z; acc[1][3] += a.y * bb.w;
            acc[2][0] += a.z * bb.x; acc[2][1] += a.z * bb.y; acc[2][2] += a.z * bb.z; acc[2][3] += a.z * bb.w;
            acc[3][0] += a.w * bb.x; acc[3][1] += a.w * bb.y; acc[3][2] += a.w * bb.z; acc[3][3] += a.w * bb.w;
        }
        __syncthreads();
    }

    float* dst = kz ? &g_simB[0][0][0] : &g_simA[0][0][0];
#pragma unroll
    for (int i = 0; i < 4; i++) {
        float4 o = make_float4(acc[i][0], acc[i][1], acc[i][2], acc[i][3]);
        *(float4*)&dst[((size_t)b * LTOP + (ty * 4 + i)) * NTOK + n0 + tx * 4] = o;
    }
}

// ---------------- K4a: per (b,l) top-32 selection, one warp per problem ----------------
// Packed key = (ordered_f32 << 32) | (NTOK - m): descending value, ascending index
// on ties -> exact jax.lax.top_k order. Iterative 32x warp argmax with incremental
// per-lane local max (only the winning lane rescans its 18 slots).
__global__ __launch_bounds__(256) void k_select() {
    int gw   = blockIdx.x * 8 + (threadIdx.x >> 5);
    int lane = threadIdx.x & 31;
    if (gw >= BATCH * LTOP) return;
    int b = gw / LTOP;
    int l = gw - b * LTOP;
    int idxl = g_idx[b][l];

    const float* __restrict__ pa = &g_simA[b][l][0];
    const float* __restrict__ pb = &g_simB[b][l][0];
    const float* __restrict__ pn = &g_ninv[b][0];

    unsigned long long key[18];
#pragma unroll
    for (int j = 0; j < 18; j++) {
        int m = lane + 32 * j;
        float v = (pa[m] + pb[m]) * pn[m];
        unsigned u = __float_as_uint(v);
        u = (u & 0x80000000u) ? ~u : (u | 0x80000000u);
        key[j] = ((unsigned long long)u << 32) | (unsigned)(NTOK - m);
        if (m == idxl) key[j] = 0ULL;   // diagonal (self) mask
    }
    unsigned long long bestk = 0ULL;
    int bestj = 0;
#pragma unroll
    for (int j = 0; j < 18; j++)
        if (key[j] > bestk) { bestk = key[j]; bestj = j; }

    for (int it = 0; it < KCL; it++) {
        unsigned long long wmax = bestk;
#pragma unroll
        for (int off = 16; off > 0; off >>= 1) {
            unsigned long long o = __shfl_xor_sync(0xffffffffu, wmax, off);
            if (o > wmax) wmax = o;
        }
        if (bestk == wmax) {            // unique winner (index embedded in key)
            g_sel[b][l][it] = NTOK - (int)(unsigned)(wmax & 0xffffffffULL);
#pragma unroll
            for (int j = 0; j < 18; j++)
                if (j == bestj) key[j] = 0ULL;
            bestk = 0ULL; bestj = 0;
#pragma unroll
            for (int j = 0; j < 18; j++)
                if (key[j] > bestk) { bestk = key[j]; bestj = j; }
        }
    }
}

// ---------------- K4b: gather + weighted merge (memory-bound) ----------------
__global__ __launch_bounds__(256) void k_merge(const float* __restrict__ x,
                                               float* __restrict__ out) {
    __shared__ int   sel[KCL];
    __shared__ float w[KCL];
    int b = blockIdx.y;
    int l = blockIdx.x;
    int t = threadIdx.x;

    if (t < KCL) {
        int m = g_sel[b][l][t];
        sel[t] = m;
        w[t]   = g_attn[b][m];
    }
    __syncthreads();

    int idxl = g_idx[b][l];
    const float4* xb = (const float4*)(x + (size_t)b * NTOK * CH);
    float4 acc = xb[(size_t)idxl * 256 + t];
#pragma unroll 8
    for (int j = 0; j < KCL; j++) {
        float4 v = xb[(size_t)sel[j] * 256 + t];
        float wj = w[j];
        acc.x += wj * v.x; acc.y += wj * v.y; acc.z += wj * v.z; acc.w += wj * v.w;
    }
    ((float4*)(out + ((size_t)b * (LTOP + 1) + l) * CH))[t] = acc;
}

// ---------------- K5a: extra partial sums, 8 token-segments per batch ----------------
__global__ __launch_bounds__(256) void k_extra_part(const float* __restrict__ x) {
    __shared__ float wa[SEGTOK];
    __shared__ int   tk[SEGTOK];
    int b = blockIdx.y;
    int s = blockIdx.x;
    int t = threadIdx.x;
    if (t < SEGTOK) {
        int tok = g_compl[b][s * SEGTOK + t];
        tk[t] = tok;
        wa[t] = g_attn[b][tok];
    }
    __syncthreads();
    const float4* xb = (const float4*)(x + (size_t)b * NTOK * CH);
    float4 acc = make_float4(0.f, 0.f, 0.f, 0.f);
#pragma unroll 7
    for (int j = 0; j < SEGTOK; j++) {
        float4 v = xb[(size_t)tk[j] * 256 + t];
        float wj = wa[j];
        acc.x += wj * v.x; acc.y += wj * v.y; acc.z += wj * v.z; acc.w += wj * v.w;
    }
    ((float4*)&g_xpart[b][s][0])[t] = acc;
}

// ---------------- K5b: reduce the 8 partials into the extra row ----------------
__global__ __launch_bounds__(256) void k_extra_red(float* __restrict__ out) {
    int b = blockIdx.x;
    int t = threadIdx.x;
    float4 acc = make_float4(0.f, 0.f, 0.f, 0.f);
#pragma unroll
    for (int s = 0; s < NSEG; s++) {
        float4 v = ((const float4*)&g_xpart[b][s][0])[t];
        acc.x += v.x; acc.y += v.y; acc.z += v.z; acc.w += v.w;
    }
    ((float4*)(out + ((size_t)b * (LTOP + 1) + LTOP) * CH))[t] = acc;
}

// ---------------- launch ----------------
extern "C" void kernel_launch(void* const* d_in, const int* in_sizes, int n_in,
                              void* d_out, int out_size) {
    const float* x       = (const float*)d_in[0];   // image_features [32,576,1024]
    const float* keys    = (const float*)d_in[1];   // keys           [32,577,1024]
    const float* queries = (const float*)d_in[2];   // queries        [32,577,1024]
    float* out = (float*)d_out;                     // [32,73,1024]

    int nwarps = BATCH * NK;                        // 18464 row-dots
    k_logits<<<(nwarps * 32 + 255) / 256, 256>>>(keys, queries);
    k_softmax_topk<<<BATCH, 640>>>();
    dim3 g3(NTOK / BN, BATCH, 2);                   // 9 x 32 x 2 = 576 blocks
    k_sim<<<g3, 288>>>(keys);
    k_select<<<(BATCH * LTOP) / 8, 256>>>();        // 288 blocks, 1 warp per (b,l)
    dim3 g4(LTOP, BATCH);                           // 72 x 32 = 2304 blocks
    k_merge<<<g4, 256>>>(x, out);
    dim3 g5(NSEG, BATCH);                           // 8 x 32 = 256 blocks
    k_extra_part<<<g5, 256>>>(x);
    k_extra_red<<<BATCH, 256>>>(out);
}

// round 5
// speedup vs baseline: 2.5791x; 1.2073x over previous
#include <cuda_runtime.h>
#include <math.h>
#include <float.h>
#include <stdint.h>

#define BATCH 32
#define NTOK  576
#define NK    577      // N + 1 (with CLS)
#define CH    1024
#define LTOP  72       // N/8
#define NCOMPL 504     // N - L
#define KCL   32
#define NSEG  8
#define SEGTOK (NCOMPL / NSEG)   // 63

// ---------------- device scratch (static, allocation-free) ----------------
__device__ float g_logits[BATCH][NK];
__device__ float g_ninv[BATCH][NTOK];
__device__ float g_attn[BATCH][NTOK];
__device__ int   g_idx[BATCH][LTOP];
__device__ int   g_compl[BATCH][NCOMPL];
__device__ float g_simA[BATCH][LTOP][NTOK];   // split-K half 0 (raw dots)
__device__ float g_simB[BATCH][LTOP][NTOK];   // split-K half 1
__device__ int   g_sel[BATCH][LTOP][KCL];
__device__ float g_xpart[BATCH][NSEG][CH];

// ---------------- K1: logits (q0 . key_r) and per-row inv-norms ----------------
__global__ __launch_bounds__(256) void k_logits(const float* __restrict__ keys,
                                                const float* __restrict__ queries) {
    int gw   = (blockIdx.x * blockDim.x + threadIdx.x) >> 5;
    int lane = threadIdx.x & 31;
    if (gw >= BATCH * NK) return;
    int b = gw / NK;
    int r = gw - b * NK;
    const float4* q = (const float4*)(queries + (size_t)b * NK * CH);
    const float4* k = (const float4*)(keys + ((size_t)b * NK + r) * CH);
    float dot = 0.f, ss = 0.f;
#pragma unroll
    for (int i = 0; i < 8; i++) {
        float4 kv = k[i * 32 + lane];
        float4 qv = q[i * 32 + lane];
        dot += kv.x * qv.x + kv.y * qv.y + kv.z * qv.z + kv.w * qv.w;
        ss  += kv.x * kv.x + kv.y * kv.y + kv.z * kv.z + kv.w * kv.w;
    }
#pragma unroll
    for (int o = 16; o > 0; o >>= 1) {
        dot += __shfl_xor_sync(0xffffffffu, dot, o);
        ss  += __shfl_xor_sync(0xffffffffu, ss, o);
    }
    if (lane == 0) {
        g_logits[b][r] = dot * 0.03125f;
        if (r >= 1) g_ninv[b][r - 1] = rsqrtf(ss + 1e-12f);
    }
}

// ---------------- K2: softmax over 577, top-L rank select, complement ----------------
__global__ __launch_bounds__(640) void k_softmax_topk() {
    __shared__ float sl[NK];
    __shared__ float sa[NTOK];
    __shared__ int   sflag[NTOK];
    __shared__ float red[640];
    int b = blockIdx.x;
    int t = threadIdx.x;

    if (t < NK) sl[t] = g_logits[b][t];
    __syncthreads();

    red[t] = (t < NK) ? sl[t] : -FLT_MAX;
    __syncthreads();
    if (t < 128) red[t] = fmaxf(red[t], red[t + 512]);
    __syncthreads();
    for (int s = 256; s > 0; s >>= 1) {
        if (t < s) red[t] = fmaxf(red[t], red[t + s]);
        __syncthreads();
    }
    float mx = red[0];
    __syncthreads();

    float e = 0.f;
    if (t < NK) { e = expf(sl[t] - mx); sl[t] = e; }
    red[t] = e;
    __syncthreads();
    if (t < 128) red[t] += red[t + 512];
    __syncthreads();
    for (int s = 256; s > 0; s >>= 1) {
        if (t < s) red[t] += red[t + s];
        __syncthreads();
    }
    float inv_sum = 1.0f / red[0];
    __syncthreads();

    if (t >= 1 && t < NK) {
        float a = sl[t] * inv_sum;
        sa[t - 1] = a;
        g_attn[b][t - 1] = a;
    }
    __syncthreads();

    if (t < NTOK) {
        float my = sa[t];
        int cnt = 0;
        for (int m = 0; m < NTOK; m++) {
            float v = sa[m];
            cnt += (v > my) || (v == my && m < t);
        }
        sflag[t] = (cnt < LTOP);
        if (cnt < LTOP) g_idx[b][cnt] = t;
    }
    __syncthreads();

    if (t < NTOK && !sflag[t]) {
        int nb = 0;
        for (int m = 0; m < t; m++) nb += sflag[m];
        g_compl[b][t - nb] = t;
    }
}

// ---------------- K3: sim GEMM via mma.sync tf32 (3xTF32 split) ----------------
// D[80x192] = A_g[80x1024] . B[192x1024]^T per (b, n-tile, K-half).
// smem float layout, LD=36 pad -> conflict-free fragment LDS:
//   A_hi [80][36] @0      A_lo @2880
//   B_hi [192][36] @5760  B_lo @12672
//   idx  int[80]  @19584
#define SIM_BN 192
#define LDA 36
#define OFF_AHI 0
#define OFF_ALO 2880
#define OFF_BHI 5760
#define OFF_BLO 12672
#define OFF_IDX 19584
#define SIM_SMEM_BYTES ((OFF_IDX + 80) * 4)

__device__ __forceinline__ void mma_tf32(float* c, const uint32_t* a, const uint32_t* bb) {
    asm volatile(
        "mma.sync.aligned.m16n8k8.row.col.f32.tf32.tf32.f32 "
        "{%0,%1,%2,%3}, {%4,%5,%6,%7}, {%8,%9}, {%0,%1,%2,%3};"
        : "+f"(c[0]), "+f"(c[1]), "+f"(c[2]), "+f"(c[3])
        : "r"(a[0]), "r"(a[1]), "r"(a[2]), "r"(a[3]), "r"(bb[0]), "r"(bb[1]));
}

__global__ __launch_bounds__(256) void k_sim_mma(const float* __restrict__ keys) {
    extern __shared__ float sm[];
    int* sidx = (int*)(sm + OFF_IDX);
    int tid = threadIdx.x;
    int b  = blockIdx.y;
    int n0 = blockIdx.x * SIM_BN;
    int kz = blockIdx.z;

    if (tid < LTOP) sidx[tid] = g_idx[b][tid];
    __syncthreads();

    const float* kb = keys + (size_t)b * NK * CH;

    // loader precompute: A = 80 rows x 8 float4 = 640 chunks; B = 192 x 8 = 1536
    const float4* aptr[3]; uint32_t aoff[3]; bool aval[3];
#pragma unroll
    for (int i = 0; i < 3; i++) {
        int q = tid + 256 * i;
        aval[i] = (q < 640);
        int row = (q < 640) ? (q >> 3) : 0;
        int c4  = q & 7;
        int tok = (row < LTOP) ? sidx[row] : sidx[0];   // pad rows duplicate, masked in epilogue
        aptr[i] = (const float4*)(kb + (size_t)(tok + 1) * CH) + c4;
        aoff[i] = row * LDA + c4 * 4;
    }
    const float4* bptr[6]; uint32_t boff[6];
#pragma unroll
    for (int i = 0; i < 6; i++) {
        int q = tid + 256 * i;
        int row = q >> 3;
        int c4  = q & 7;
        bptr[i] = (const float4*)(kb + (size_t)(1 + n0 + row) * CH) + c4;
        boff[i] = row * LDA + c4 * 4;
    }

    int w = tid >> 5, lane = tid & 31;
    int g = lane >> 2, t4 = lane & 3;
    int nb = w * 24;                 // warp's 24-col strip

    float acc[5][3][4];
#pragma unroll
    for (int i = 0; i < 5; i++)
#pragma unroll
        for (int j = 0; j < 3; j++)
#pragma unroll
            for (int c = 0; c < 4; c++) acc[i][j][c] = 0.f;

    int k4 = kz * 128;               // float4 index into 1024-float rows
    for (int s = 0; s < 16; s++, k4 += 8) {
#pragma unroll
        for (int i = 0; i < 3; i++) {
            if (aval[i]) {
                float4 v = aptr[i][k4];
                float4 h, l;
                h.x = __uint_as_float(__float_as_uint(v.x) & 0xffffe000u);
                h.y = __uint_as_float(__float_as_uint(v.y) & 0xffffe000u);
                h.z = __uint_as_float(__float_as_uint(v.z) & 0xffffe000u);
                h.w = __uint_as_float(__float_as_uint(v.w) & 0xffffe000u);
                l.x = v.x - h.x; l.y = v.y - h.y; l.z = v.z - h.z; l.w = v.w - h.w;
                *(float4*)&sm[OFF_AHI + aoff[i]] = h;
                *(float4*)&sm[OFF_ALO + aoff[i]] = l;
            }
        }
#pragma unroll
        for (int i = 0; i < 6; i++) {
            float4 v = bptr[i][k4];
            float4 h, l;
            h.x = __uint_as_float(__float_as_uint(v.x) & 0xffffe000u);
            h.y = __uint_as_float(__float_as_uint(v.y) & 0xffffe000u);
            h.z = __uint_as_float(__float_as_uint(v.z) & 0xffffe000u);
            h.w = __uint_as_float(__float_as_uint(v.w) & 0xffffe000u);
            l.x = v.x - h.x; l.y = v.y - h.y; l.z = v.z - h.z; l.w = v.w - h.w;
            *(float4*)&sm[OFF_BHI + boff[i]] = h;
            *(float4*)&sm[OFF_BLO + boff[i]] = l;
        }
        __syncthreads();

#pragma unroll
        for (int s8 = 0; s8 < 4; s8++) {
            int kk = s8 * 8;
            uint32_t bh[3][2], bl[3][2];
#pragma unroll
            for (int j = 0; j < 3; j++) {
                int base = (nb + j * 8 + g) * LDA + kk + t4;
                bh[j][0] = __float_as_uint(sm[OFF_BHI + base]);
                bh[j][1] = __float_as_uint(sm[OFF_BHI + base + 4]);
                bl[j][0] = __float_as_uint(sm[OFF_BLO + base]);
                bl[j][1] = __float_as_uint(sm[OFF_BLO + base + 4]);
            }
#pragma unroll
            for (int mt = 0; mt < 5; mt++) {
                int ab = (mt * 16 + g) * LDA + kk + t4;
                uint32_t ah[4], al[4];
                ah[0] = __float_as_uint(sm[OFF_AHI + ab]);
                ah[1] = __float_as_uint(sm[OFF_AHI + ab + 8 * LDA]);
                ah[2] = __float_as_uint(sm[OFF_AHI + ab + 4]);
                ah[3] = __float_as_uint(sm[OFF_AHI + ab + 8 * LDA + 4]);
                al[0] = __float_as_uint(sm[OFF_ALO + ab]);
                al[1] = __float_as_uint(sm[OFF_ALO + ab + 8 * LDA]);
                al[2] = __float_as_uint(sm[OFF_ALO + ab + 4]);
                al[3] = __float_as_uint(sm[OFF_ALO + ab + 8 * LDA + 4]);
#pragma unroll
                for (int j = 0; j < 3; j++) {
                    mma_tf32(acc[mt][j], ah, bh[j]);
                    mma_tf32(acc[mt][j], ah, bl[j]);
                    mma_tf32(acc[mt][j], al, bh[j]);
                }
            }
        }
        __syncthreads();
    }

    // epilogue: c0,c1 -> (row g, cols 2t,2t+1); c2,c3 -> row g+8
    float* base = kz ? &g_simB[0][0][0] : &g_simA[0][0][0];
#pragma unroll
    for (int mt = 0; mt < 5; mt++) {
        int m0 = mt * 16 + g;
        int m1 = m0 + 8;
#pragma unroll
        for (int j = 0; j < 3; j++) {
            int n = n0 + nb + j * 8 + 2 * t4;
            if (m0 < LTOP)
                *(float2*)&base[((size_t)b * LTOP + m0) * NTOK + n] = make_float2(acc[mt][j][0], acc[mt][j][1]);
            if (m1 < LTOP)
                *(float2*)&base[((size_t)b * LTOP + m1) * NTOK + n] = make_float2(acc[mt][j][2], acc[mt][j][3]);
        }
    }
}

// ---------------- K4a: per (b,l) top-32 selection, one warp per problem ----------------
__device__ __forceinline__ unsigned long long umax64(unsigned long long a, unsigned long long b) { return a > b ? a : b; }
__device__ __forceinline__ unsigned long long umin64(unsigned long long a, unsigned long long b) { return a < b ? a : b; }

__global__ __launch_bounds__(256) void k_select() {
    int gw   = blockIdx.x * 8 + (threadIdx.x >> 5);
    int lane = threadIdx.x & 31;
    if (gw >= BATCH * LTOP) return;
    int b = gw / LTOP;
    int l = gw - b * LTOP;
    int idxl = g_idx[b][l];

    const float* __restrict__ pa = &g_simA[b][l][0];
    const float* __restrict__ pb = &g_simB[b][l][0];
    const float* __restrict__ pn = &g_ninv[b][0];

    unsigned long long key[18];
    unsigned long long s0 = 0, s1 = 0, s2 = 0, s3 = 0;
#pragma unroll
    for (int j = 0; j < 18; j++) {
        int m = lane + 32 * j;
        float v = (pa[m] + pb[m]) * pn[m];
        unsigned u = __float_as_uint(v);
        u = (u & 0x80000000u) ? ~u : (u | 0x80000000u);
        unsigned long long kk = ((unsigned long long)u << 32) | (unsigned)(NTOK - m);
        if (m == idxl) kk = 0ULL;
        key[j] = kk;
        unsigned long long t0 = umax64(s0, kk), b0 = umin64(s0, kk); s0 = t0;
        unsigned long long t1 = umax64(s1, b0), b1 = umin64(s1, b0); s1 = t1;
        unsigned long long t2 = umax64(s2, b1), b2 = umin64(s2, b1); s2 = t2;
        s3 = umax64(s3, b2);
    }

    int c = 0;
    unsigned long long cand = s0;
    for (int it = 0; it < KCL; it++) {
        unsigned long long wmax = cand;
#pragma unroll
        for (int off = 16; off > 0; off >>= 1) {
            unsigned long long o = __shfl_xor_sync(0xffffffffu, wmax, off);
            if (o > wmax) wmax = o;
        }
        if (cand == wmax) {            // unique winner (index embedded)
            g_sel[b][l][it] = NTOK - (int)(unsigned)(wmax & 0xffffffffULL);
            c++;
            if (c == 1)      cand = s1;
            else if (c == 2) cand = s2;
            else if (c == 3) cand = s3;
            else {
                unsigned long long nf = 0;
#pragma unroll
                for (int j = 0; j < 18; j++)
                    if (key[j] < wmax) nf = umax64(nf, key[j]);
                cand = nf;
            }
        }
    }
}

// ---------------- K4b: gather + weighted merge (memory-bound) ----------------
__global__ __launch_bounds__(256) void k_merge(const float* __restrict__ x,
                                               float* __restrict__ out) {
    __shared__ int   sel[KCL];
    __shared__ float w[KCL];
    int b = blockIdx.y;
    int l = blockIdx.x;
    int t = threadIdx.x;

    if (t < KCL) {
        int m = g_sel[b][l][t];
        sel[t] = m;
        w[t]   = g_attn[b][m];
    }
    __syncthreads();

    int idxl = g_idx[b][l];
    const float4* xb = (const float4*)(x + (size_t)b * NTOK * CH);
    float4 acc = xb[(size_t)idxl * 256 + t];
#pragma unroll 8
    for (int j = 0; j < KCL; j++) {
        float4 v = xb[(size_t)sel[j] * 256 + t];
        float wj = w[j];
        acc.x += wj * v.x; acc.y += wj * v.y; acc.z += wj * v.z; acc.w += wj * v.w;
    }
    ((float4*)(out + ((size_t)b * (LTOP + 1) + l) * CH))[t] = acc;
}

// ---------------- K5a: extra partial sums, 8 token-segments per batch ----------------
__global__ __launch_bounds__(256) void k_extra_part(const float* __restrict__ x) {
    __shared__ float wa[SEGTOK];
    __shared__ int   tk[SEGTOK];
    int b = blockIdx.y;
    int s = blockIdx.x;
    int t = threadIdx.x;
    if (t < SEGTOK) {
        int tok = g_compl[b][s * SEGTOK + t];
        tk[t] = tok;
        wa[t] = g_attn[b][tok];
    }
    __syncthreads();
    const float4* xb = (const float4*)(x + (size_t)b * NTOK * CH);
    float4 acc = make_float4(0.f, 0.f, 0.f, 0.f);
#pragma unroll 7
    for (int j = 0; j < SEGTOK; j++) {
        float4 v = xb[(size_t)tk[j] * 256 + t];
        float wj = wa[j];
        acc.x += wj * v.x; acc.y += wj * v.y; acc.z += wj * v.z; acc.w += wj * v.w;
    }
    ((float4*)&g_xpart[b][s][0])[t] = acc;
}

// ---------------- K5b: reduce the 8 partials into the extra row ----------------
__global__ __launch_bounds__(256) void k_extra_red(float* __restrict__ out) {
    int b = blockIdx.x;
    int t = threadIdx.x;
    float4 acc = make_float4(0.f, 0.f, 0.f, 0.f);
#pragma unroll
    for (int s = 0; s < NSEG; s++) {
        float4 v = ((const float4*)&g_xpart[b][s][0])[t];
        acc.x += v.x; acc.y += v.y; acc.z += v.z; acc.w += v.w;
    }
    ((float4*)(out + ((size_t)b * (LTOP + 1) + LTOP) * CH))[t] = acc;
}

// ---------------- launch ----------------
extern "C" void kernel_launch(void* const* d_in, const int* in_sizes, int n_in,
                              void* d_out, int out_size) {
    const float* x       = (const float*)d_in[0];   // image_features [32,576,1024]
    const float* keys    = (const float*)d_in[1];   // keys           [32,577,1024]
    const float* queries = (const float*)d_in[2];   // queries        [32,577,1024]
    float* out = (float*)d_out;                     // [32,73,1024]

    static int smem_set = 0;
    if (!smem_set) {
        cudaFuncSetAttribute(k_sim_mma, cudaFuncAttributeMaxDynamicSharedMemorySize, SIM_SMEM_BYTES);
        smem_set = 1;
    }

    int nwarps = BATCH * NK;
    k_logits<<<(nwarps * 32 + 255) / 256, 256>>>(keys, queries);
    k_softmax_topk<<<BATCH, 640>>>();
    dim3 g3(NTOK / SIM_BN, BATCH, 2);               // 3 x 32 x 2 = 192 blocks
    k_sim_mma<<<g3, 256, SIM_SMEM_BYTES>>>(keys);
    k_select<<<(BATCH * LTOP) / 8, 256>>>();        // 288 blocks, 1 warp per (b,l)
    dim3 g4(LTOP, BATCH);
    k_merge<<<g4, 256>>>(x, out);
    dim3 g5(NSEG, BATCH);
    k_extra_part<<<g5, 256>>>(x);
    k_extra_red<<<BATCH, 256>>>(out);
}